// round 7
// baseline (speedup 1.0000x reference)
#include <cuda_runtime.h>
#include <cuda_bf16.h>
#include <cstdint>

#define N_NODES 5
#define EMB 16
#define HID 32

// LUT[c][e] : value for a cell whose game_state char == c, c in 0..5.
__device__ float g_lut[6 * EMB];

// ---------------------------------------------------------------------------
// Kernel 1: tiny GCN on 5 nodes -> fill g_lut. One block, 192 threads.
// ---------------------------------------------------------------------------
__global__ void gcn_build_lut(const float* __restrict__ emb,   // [5,16]
                              const float* __restrict__ A,     // [5,5]
                              const float* __restrict__ W0,    // [32,16]
                              const float* __restrict__ W1,    // [32,32]
                              const float* __restrict__ W2,    // [32,32]
                              const float* __restrict__ Wf,    // [16,32]
                              const float* __restrict__ bf)    // [16]
{
    __shared__ float sE[N_NODES * EMB];
    __shared__ float sA[N_NODES * N_NODES];
    __shared__ float sW0[HID * EMB];
    __shared__ float sW1[HID * HID];
    __shared__ float sW2[HID * HID];
    __shared__ float sWf[EMB * HID];
    __shared__ float sbf[EMB];
    __shared__ float x0[N_NODES][EMB];
    __shared__ float h[N_NODES][HID];
    __shared__ float y[N_NODES][HID];

    const int t = threadIdx.x;
    const int NT = blockDim.x;

    for (int i = t; i < N_NODES * EMB; i += NT) sE[i] = emb[i];
    for (int i = t; i < N_NODES * N_NODES; i += NT) sA[i] = A[i];
    for (int i = t; i < HID * EMB; i += NT) sW0[i] = W0[i];
    for (int i = t; i < HID * HID; i += NT) sW1[i] = W1[i];
    for (int i = t; i < HID * HID; i += NT) sW2[i] = W2[i];
    for (int i = t; i < EMB * HID; i += NT) sWf[i] = Wf[i];
    for (int i = t; i < EMB; i += NT) sbf[i] = bf[i];
    __syncthreads();

    if (t < N_NODES * EMB) {
        int i = t / EMB, j = t % EMB;
        float s = 0.f;
        #pragma unroll
        for (int k = 0; k < N_NODES; k++) s += sA[i * N_NODES + k] * sE[k * EMB + j];
        x0[i][j] = s;
    }
    __syncthreads();

    if (t < N_NODES * HID) {
        int i = t / HID, o = t % HID;
        float s = 0.f;
        #pragma unroll
        for (int j = 0; j < EMB; j++) s += x0[i][j] * sW0[o * EMB + j];
        h[i][o] = fmaxf(s, 0.f);
    }
    __syncthreads();

    if (t < N_NODES * HID) {
        int i = t / HID, o = t % HID;
        float s = 0.f;
        #pragma unroll
        for (int k = 0; k < N_NODES; k++) s += sA[i * N_NODES + k] * h[k][o];
        y[i][o] = s;
    }
    __syncthreads();
    if (t < N_NODES * HID) {
        int i = t / HID, o = t % HID;
        float s = 0.f;
        #pragma unroll
        for (int j = 0; j < HID; j++) s += y[i][j] * sW1[o * HID + j];
        h[i][o] = fmaxf(s, 0.f);
    }
    __syncthreads();

    if (t < N_NODES * HID) {
        int i = t / HID, o = t % HID;
        float s = 0.f;
        #pragma unroll
        for (int k = 0; k < N_NODES; k++) s += sA[i * N_NODES + k] * h[k][o];
        y[i][o] = s;
    }
    __syncthreads();
    if (t < N_NODES * HID) {
        int i = t / HID, o = t % HID;
        float s = 0.f;
        #pragma unroll
        for (int j = 0; j < HID; j++) s += y[i][j] * sW2[o * HID + j];
        h[i][o] = fmaxf(s, 0.f);
    }
    __syncthreads();

    if (t < N_NODES * EMB) {
        int i = t / EMB, e = t % EMB;
        float s = sbf[e];
        #pragma unroll
        for (int j = 0; j < HID; j++) s += h[i][j] * sWf[e * HID + j];
        g_lut[(i + 1) * EMB + e] = s;
    }
    if (t < EMB) g_lut[t] = sE[t];
}

// ---------------------------------------------------------------------------
// Kernel 2: scatter with TMA bulk stores.
// Each block builds a 32KB output tile in smem (LDS LUT -> STS.128,
// conflict-free), then a single cp.async.bulk 1D store ships the whole tile
// to GMEM — removing all per-lane STG wavefronts from the L1tex write path.
// ---------------------------------------------------------------------------
#define TPB 256
#define QPT 8
#define TILE (TPB * QPT)            // 2048 quads = 32KB per block
#define TILE_BYTES (TILE * 16)

__device__ __forceinline__ uint32_t smem_u32(const void* p) {
    uint32_t a;
    asm("{ .reg .u64 t; cvta.to.shared.u64 t, %1; cvt.u32.u64 %0, t; }"
        : "=r"(a) : "l"(p));
    return a;
}

__global__ void __launch_bounds__(TPB) scatter_lut(const int* __restrict__ gs,
                                                   float4* __restrict__ out,
                                                   int nquads)
{
    __shared__ float4 slut[6 * 4];       // 96 floats
    __shared__ __align__(128) float4 stile[TILE];   // 32KB tile

    const int tid = threadIdx.x;
    if (tid < 24) slut[tid] = reinterpret_cast<const float4*>(g_lut)[tid];
    __syncthreads();

    const int tile_base = blockIdx.x * TILE;        // first quad of this tile
    const int q = tid & 3;                          // lane-within-cell
    const float4* __restrict__ lutq = slut + q;
    const int*    __restrict__ g    = gs + ((tile_base + tid) >> 2);

    if (tile_base + TILE <= nquads) {
        // ---- fast path: full tile (always taken for the bench shape) ----
        int c[QPT];
        #pragma unroll
        for (int u = 0; u < QPT; u++) c[u] = __ldg(g + u * (TPB >> 2));
        #pragma unroll
        for (int u = 0; u < QPT; u++) stile[u * TPB + tid] = lutq[c[u] * 4];

        __syncthreads();
        // order generic STS writes before the async-proxy TMA read
        asm volatile("fence.proxy.async.shared::cta;" ::: "memory");

        if (tid == 0) {
            uint32_t src = smem_u32(stile);
            const float4* dst = out + tile_base;
            asm volatile(
                "cp.async.bulk.global.shared::cta.bulk_group [%0], [%1], %2;"
                :: "l"(dst), "r"(src), "n"(TILE_BYTES) : "memory");
            asm volatile("cp.async.bulk.commit_group;" ::: "memory");
            asm volatile("cp.async.bulk.wait_group 0;" ::: "memory");
        }
    } else {
        // ---- tail: plain guarded stores ----
        #pragma unroll
        for (int u = 0; u < QPT; u++) {
            int idx = tile_base + u * TPB + tid;
            if (idx < nquads) {
                int c = __ldg(gs + (idx >> 2));
                out[idx] = lutq[c * 4];
            }
        }
    }
}

// ---------------------------------------------------------------------------
extern "C" void kernel_launch(void* const* d_in, const int* in_sizes, int n_in,
                              void* d_out, int out_size)
{
    const int*   gs  = (const int*)d_in[0];    // game_state [256,128,128]
    const float* emb = (const float*)d_in[1];  // [5,16]
    const float* A   = (const float*)d_in[2];  // [5,5]
    const float* W0  = (const float*)d_in[3];  // [32,16]
    const float* W1  = (const float*)d_in[4];  // [32,32]
    const float* W2  = (const float*)d_in[5];  // [32,32]
    const float* Wf  = (const float*)d_in[6];  // [16,32]
    const float* bf  = (const float*)d_in[7];  // [16]
    float4* out = (float4*)d_out;

    const int ncells = in_sizes[0];            // 4,194,304
    const int nquads = ncells * 4;             // 16,777,216 float4s

    gcn_build_lut<<<1, 192>>>(emb, A, W0, W1, W2, Wf, bf);

    const int blocks = (nquads + TILE - 1) / TILE;   // 8192
    scatter_lut<<<blocks, TPB>>>(gs, out, nquads);
}

// round 8
// speedup vs baseline: 1.2260x; 1.2260x over previous
#include <cuda_runtime.h>
#include <cuda_bf16.h>

#define N_NODES 5
#define EMB 16
#define HID 32

// LUT[c][e] : value for a cell whose game_state char == c, c in 0..5.
// c == 0    -> emb_table[0][e]   (gse fallback)
// c in 1..5 -> node_emb[c-1][e]  (GCN output rows)
__device__ float g_lut[6 * EMB];

// ---------------------------------------------------------------------------
// Kernel 1: tiny GCN on 5 nodes -> fill g_lut. One block, 160 threads
// (= N_NODES*HID, the widest stage). Weights prefetched to smem in parallel
// so the 6 dependent stages pay one global-load latency total.
// ---------------------------------------------------------------------------
__global__ void gcn_build_lut(const float* __restrict__ emb,   // [5,16]
                              const float* __restrict__ A,     // [5,5]
                              const float* __restrict__ W0,    // [32,16]
                              const float* __restrict__ W1,    // [32,32]
                              const float* __restrict__ W2,    // [32,32]
                              const float* __restrict__ Wf,    // [16,32]
                              const float* __restrict__ bf)    // [16]
{
    __shared__ float sE[N_NODES * EMB];
    __shared__ float sA[N_NODES * N_NODES];
    __shared__ float sW0[HID * EMB];
    __shared__ float sW1[HID * HID];
    __shared__ float sW2[HID * HID];
    __shared__ float sWf[EMB * HID];
    __shared__ float sbf[EMB];
    __shared__ float x0[N_NODES][EMB];
    __shared__ float h[N_NODES][HID];
    __shared__ float y[N_NODES][HID];

    const int t = threadIdx.x;
    const int NT = blockDim.x;

    for (int i = t; i < N_NODES * EMB; i += NT) sE[i] = emb[i];
    for (int i = t; i < N_NODES * N_NODES; i += NT) sA[i] = A[i];
    for (int i = t; i < HID * EMB; i += NT) sW0[i] = W0[i];
    for (int i = t; i < HID * HID; i += NT) sW1[i] = W1[i];
    for (int i = t; i < HID * HID; i += NT) sW2[i] = W2[i];
    for (int i = t; i < EMB * HID; i += NT) sWf[i] = Wf[i];
    for (int i = t; i < EMB; i += NT) sbf[i] = bf[i];
    __syncthreads();

    // x0 = A @ emb_table  [5,16]
    if (t < N_NODES * EMB) {
        int i = t / EMB, j = t % EMB;
        float s = 0.f;
        #pragma unroll
        for (int k = 0; k < N_NODES; k++) s += sA[i * N_NODES + k] * sE[k * EMB + j];
        x0[i][j] = s;
    }
    __syncthreads();

    // h = relu(x0 @ W0^T)  [5,32]  (all 160 threads active)
    {
        int i = t / HID, o = t % HID;
        float s = 0.f;
        #pragma unroll
        for (int j = 0; j < EMB; j++) s += x0[i][j] * sW0[o * EMB + j];
        h[i][o] = fmaxf(s, 0.f);
    }
    __syncthreads();

    // round 1: y = A@h ; h = relu(y @ W1^T)
    {
        int i = t / HID, o = t % HID;
        float s = 0.f;
        #pragma unroll
        for (int k = 0; k < N_NODES; k++) s += sA[i * N_NODES + k] * h[k][o];
        y[i][o] = s;
    }
    __syncthreads();
    {
        int i = t / HID, o = t % HID;
        float s = 0.f;
        #pragma unroll
        for (int j = 0; j < HID; j++) s += y[i][j] * sW1[o * HID + j];
        h[i][o] = fmaxf(s, 0.f);
    }
    __syncthreads();

    // round 2: y = A@h ; h = relu(y @ W2^T)
    {
        int i = t / HID, o = t % HID;
        float s = 0.f;
        #pragma unroll
        for (int k = 0; k < N_NODES; k++) s += sA[i * N_NODES + k] * h[k][o];
        y[i][o] = s;
    }
    __syncthreads();
    {
        int i = t / HID, o = t % HID;
        float s = 0.f;
        #pragma unroll
        for (int j = 0; j < HID; j++) s += y[i][j] * sW2[o * HID + j];
        h[i][o] = fmaxf(s, 0.f);
    }
    __syncthreads();

    // LUT rows 1..5 : h @ Wf^T + bf  [5,16]
    if (t < N_NODES * EMB) {
        int i = t / EMB, e = t % EMB;
        float s = sbf[e];
        #pragma unroll
        for (int j = 0; j < HID; j++) s += h[i][j] * sWf[e * HID + j];
        g_lut[(i + 1) * EMB + e] = s;
    }
    // LUT row 0 : emb_table row 0 (gs==0 path)
    if (t < EMB) g_lut[t] = sE[t];
}

// ---------------------------------------------------------------------------
// Kernel 2: HBM-streaming scatter (best-measured configuration).
// Block tile = 2048 quads (32KB out). Thread t handles quads {t + u*256}:
// every STG.128 is a fully-coalesced 512B/warp stream. LUT lives in smem
// (LDS.128, off the L1 global path); output goes out via streaming __stcs.
// Measured at the chip's practical DRAM write ceiling (~5 TB/s).
// ---------------------------------------------------------------------------
#define TPB 256
#define QPT 8
#define TILE (TPB * QPT)   // 2048 quads per block

__global__ void __launch_bounds__(TPB) scatter_lut(const int* __restrict__ gs,
                                                   float4* __restrict__ out,
                                                   int nquads)
{
    __shared__ float4 slut[6 * 4];   // 6 rows x 4 quads = 96 floats

    const int tid = threadIdx.x;
    if (tid < 24) {
        slut[tid] = reinterpret_cast<const float4*>(g_lut)[tid];
    }
    __syncthreads();

    const int base = blockIdx.x * TILE + tid;   // quad index, iter 0
    const int q    = tid & 3;                   // lane-within-cell (TILE%4==0)

    const float4* __restrict__ lutq = slut + q;
    const int*    __restrict__ g    = gs + (base >> 2);
    float4*       __restrict__ o    = out + base;

    if (base + (QPT - 1) * TPB < nquads) {
        // fast path (always taken for the bench shape): 8 independent strips
        int c[QPT];
        #pragma unroll
        for (int u = 0; u < QPT; u++) c[u] = __ldg(g + u * (TPB >> 2));
        #pragma unroll
        for (int u = 0; u < QPT; u++) {
            float4 v = lutq[c[u] * 4];
            __stcs(o + u * TPB, v);
        }
    } else {
        #pragma unroll
        for (int u = 0; u < QPT; u++) {
            int idx = base + u * TPB;
            if (idx < nquads) {
                int c = __ldg(g + u * (TPB >> 2));
                __stcs(o + u * TPB, lutq[c * 4]);
            }
        }
    }
}

// ---------------------------------------------------------------------------
extern "C" void kernel_launch(void* const* d_in, const int* in_sizes, int n_in,
                              void* d_out, int out_size)
{
    const int*   gs  = (const int*)d_in[0];    // game_state [256,128,128]
    const float* emb = (const float*)d_in[1];  // [5,16]
    const float* A   = (const float*)d_in[2];  // [5,5]
    const float* W0  = (const float*)d_in[3];  // [32,16]
    const float* W1  = (const float*)d_in[4];  // [32,32]
    const float* W2  = (const float*)d_in[5];  // [32,32]
    const float* Wf  = (const float*)d_in[6];  // [16,32]
    const float* bf  = (const float*)d_in[7];  // [16]
    float4* out = (float4*)d_out;

    const int ncells = in_sizes[0];            // 4,194,304
    const int nquads = ncells * 4;             // 16,777,216 float4 stores

    gcn_build_lut<<<1, 160>>>(emb, A, W0, W1, W2, Wf, bf);

    const int blocks = (nquads + TILE - 1) / TILE;   // 8192
    scatter_lut<<<blocks, TPB>>>(gs, out, nquads);
}